// round 8
// baseline (speedup 1.0000x reference)
#include <cuda_runtime.h>
#include <cuda_fp16.h>
#include <cstdint>

// ---------------------------------------------------------------------------
// out = concat( relu(A@relu(A@F)), A@(A@G) ), A:[8192,8192] f32, F,G:[8192,64]
// Per layer: fused GEMM C[8192,128] = A @ Bt^T, relu on cols [0,64).
// fp16 mma.m16n8k16. 8 MMA warps (2/SMSP, 32x32 tiles, mutual latency hiding)
// + 4 producer warps. Producers convert A fp32->fp16 (x2^13) in-register via
// a 4-deep LDG pipeline; B is fp16 via cp.async. Crossbar 48KB/stage < tensor.
// ---------------------------------------------------------------------------

#define NN      8192
#define NB      128
#define MT      64              // M rows per CTA -> 128 CTAs
#define KT      32              // K per stage
#define STAGES  8
#define KIT     (NN / KT)       // 256
#define A_PITCH 80              // bytes per A smem row (fp16 k32 + pad)
#define B_PITCH 64              // bytes per B smem row (fp16 k32)
#define A_STG_B (64 * A_PITCH)  // 5120
#define B_STG_B (128 * B_PITCH) // 8192
#define STG_B   (A_STG_B + B_STG_B)        // 13312
#define SMEM_BYTES (STAGES * STG_B)        // 106496

__device__ __half g_bth1[NB * NN];   // layer-1 B, fp16 chunk-permuted
__device__ __half g_bth2[NB * NN];   // layer-1 out (x2^6) = layer-2 B

// chunk permutation within each k32 block (2-element chunks):
// chunk j -> position (j%4)*4 + j/4
__device__ __forceinline__ int kperm2(int k) {
    int j = (k >> 1) & 15;
    int p = ((j & 3) << 2) | (j >> 2);
    return (k & ~31) | (p << 1) | (k & 1);
}

__device__ __forceinline__ uint32_t smem_u32(const void* p) {
    uint32_t a;
    asm("{ .reg .u64 t; cvta.to.shared.u64 t, %1; cvt.u32.u64 %0, t; }"
        : "=r"(a) : "l"(p));
    return a;
}

// pack two fp32 -> fp16x2 (lo = first arg)
__device__ __forceinline__ uint32_t pack_h2(float lo, float hi) {
    uint32_t d;
    asm("cvt.rn.f16x2.f32 %0, %1, %2;" : "=r"(d) : "f"(hi), "f"(lo));
    return d;
}

#define CP_ASYNC16(dst, src) \
    asm volatile("cp.async.cg.shared.global [%0], [%1], 16;" \
                 :: "r"(dst), "l"(src) : "memory")

#define MBAR_INIT(addr, cnt) \
    asm volatile("mbarrier.init.shared.b64 [%0], %1;" :: "r"(addr), "r"(cnt) : "memory")
#define MBAR_ARRIVE(addr) \
    asm volatile("mbarrier.arrive.release.cta.shared::cta.b64 _, [%0];" \
                 :: "r"(addr) : "memory")
#define CP_ASYNC_MBAR_ARRIVE(addr) \
    asm volatile("cp.async.mbarrier.arrive.noinc.shared::cta.b64 [%0];" \
                 :: "r"(addr) : "memory")

#define MBAR_WAIT(addr, parity) do {                                          \
    uint32_t _mb = (addr); uint32_t _ph = (parity); uint32_t _done;           \
    asm volatile("{\n\t.reg .pred p;\n\t"                                     \
        "mbarrier.try_wait.parity.acquire.cta.shared::cta.b64 p, [%1], %2;\n\t"\
        "selp.b32 %0, 1, 0, p;\n\t}"                                          \
        : "=r"(_done) : "r"(_mb), "r"(_ph) : "memory");                       \
    if (!_done) {                                                             \
        asm volatile("{\n\t.reg .pred P1;\n\t"                                \
            "WL_%=:\n\t"                                                      \
            "mbarrier.try_wait.parity.acquire.cta.shared::cta.b64 P1, [%0], %1, 0x989680;\n\t" \
            "@P1 bra.uni WD_%=;\n\t"                                          \
            "bra.uni WL_%=;\n\t"                                              \
            "WD_%=:\n\t}"                                                     \
            :: "r"(_mb), "r"(_ph) : "memory");                                \
    }                                                                         \
} while (0)

__device__ __forceinline__ void mma_f16(float* c, const uint32_t* a,
                                        uint32_t b0, uint32_t b1) {
    asm volatile(
        "mma.sync.aligned.m16n8k16.row.col.f32.f16.f16.f32 "
        "{%0,%1,%2,%3}, {%4,%5,%6,%7}, {%8,%9}, {%0,%1,%2,%3};"
        : "+f"(c[0]), "+f"(c[1]), "+f"(c[2]), "+f"(c[3])
        : "r"(a[0]), "r"(a[1]), "r"(a[2]), "r"(a[3]), "r"(b0), "r"(b1));
}

// ---------------------------------------------------------------------------
__global__ void pack_bt_kernel(const float* __restrict__ F,
                               const float* __restrict__ G,
                               __half* __restrict__ Bt) {
    __shared__ float tile[32][33];
    int kb = blockIdx.x * 32;
    int nb = blockIdx.y * 32;
    int tx = threadIdx.x, ty = threadIdx.y;   // block (32, 8)
    #pragma unroll
    for (int r = ty; r < 32; r += 8) {
        int k = kb + r, n = nb + tx;
        float v = (n < 64) ? F[(size_t)k * 64 + n] : G[(size_t)k * 64 + (n - 64)];
        tile[r][tx] = v;
    }
    __syncthreads();
    #pragma unroll
    for (int r = ty; r < 32; r += 8) {
        int n = nb + r, k = kb + tx;
        Bt[(size_t)n * NN + kperm2(k)] = __float2half_rn(tile[tx][r]);
    }
}

// ---------------------------------------------------------------------------
__global__ void __launch_bounds__(384, 1)
gemm_layer(const float* __restrict__ A, const __half* __restrict__ Bt,
           __half* __restrict__ outT, float* __restrict__ outR, float scale) {
    extern __shared__ char smem[];
    __shared__ __align__(8) uint64_t mbar[2 * STAGES];

    const int tid  = threadIdx.x;
    const int lane = tid & 31;
    const int w    = tid >> 5;
    const int m0   = blockIdx.x * MT;
    const uint32_t sbase = smem_u32(smem);
    const uint32_t mb    = smem_u32(mbar);
    const int r4 = lane >> 2;
    const int c4 = lane & 3;

    if (tid == 0) {
        #pragma unroll
        for (int s = 0; s < STAGES; s++) {
            MBAR_INIT(mb + 8 * s, 256);                 // full: 128 STS + 128 cp
            MBAR_INIT(mb + 8 * (STAGES + s), 256);      // empty: 256 consumers
        }
    }
    __syncthreads();

    if (w >= 8) {
        // ================= producers (warps 8-11) =================
        const int t = tid - 256;
        const int arow = t >> 3, akc = t & 7;   // A chunk base (row, k-chunk)
        const int bcol = t >> 2, bq  = t & 3;   // B chunk base

        float4 aBuf[4][4];                       // [slot][j]
        auto ldgA = [&](int it, float4 (&buf)[4]) {
            const int k0 = it * KT;
            #pragma unroll
            for (int j = 0; j < 4; j++) {
                int row = arow + 16 * j;
                buf[j] = *(const float4*)(A + (size_t)(m0 + row) * NN
                                            + k0 + akc * 4);
            }
        };
        auto stsA = [&](int s, float4 (&buf)[4]) {
            const uint32_t base = sbase + (uint32_t)s * STG_B;
            #pragma unroll
            for (int j = 0; j < 4; j++) {
                int row = arow + 16 * j;
                uint32_t lo = pack_h2(buf[j].x * 8192.f, buf[j].y * 8192.f);
                uint32_t hi = pack_h2(buf[j].z * 8192.f, buf[j].w * 8192.f);
                asm volatile("st.shared.v2.b32 [%0], {%1, %2};"
                             :: "r"(base + (uint32_t)(row * A_PITCH + akc * 8)),
                                "r"(lo), "r"(hi) : "memory");
            }
        };
        auto cpB = [&](int it) {
            const int k0 = it * KT;
            const uint32_t bbase = sbase + (uint32_t)(it & (STAGES - 1)) * STG_B
                                   + A_STG_B;
            #pragma unroll
            for (int j = 0; j < 4; j++) {
                int col = bcol + 32 * j;
                const __half* src = Bt + (size_t)col * NN + k0 + bq * 8;
                CP_ASYNC16(bbase + (uint32_t)(col * B_PITCH + bq * 16), src);
            }
        };

        ldgA(0, aBuf[0]); ldgA(1, aBuf[1]); ldgA(2, aBuf[2]); ldgA(3, aBuf[3]);

        for (int itb = 0; itb < KIT; itb += 4) {
            #pragma unroll
            for (int u = 0; u < 4; u++) {
                const int it = itb + u;
                const int s = it & (STAGES - 1);
                const int r = it >> 3;
                if (r > 0) MBAR_WAIT(mb + 8 * (STAGES + s), (r - 1) & 1);
                stsA(s, aBuf[u]);
                MBAR_ARRIVE(mb + 8 * s);            // release: covers STS
                cpB(it);
                CP_ASYNC_MBAR_ARRIVE(mb + 8 * s);   // covers this iter's cp
                if (it + 4 < KIT) ldgA(it + 4, aBuf[u]);
            }
        }
        return;
    }

    // ============ MMA warps (0-7): 32 rows x 32 cols each ============
    const int wm = w & 1;        // rows wm*32 .. +31
    const int wn = w >> 1;       // cols wn*32 .. +31

    float acc[2][4][4];
    #pragma unroll
    for (int mi = 0; mi < 2; mi++)
        #pragma unroll
        for (int ni = 0; ni < 4; ni++)
            #pragma unroll
            for (int j = 0; j < 4; j++) acc[mi][ni][j] = 0.f;

    const uint32_t aoff = (uint32_t)((wm * 32 + r4) * A_PITCH + 4 * c4);
    const uint32_t boff = (uint32_t)((wn * 32 + r4) * B_PITCH + 16 * c4);

    for (int it = 0; it < KIT; it++) {
        const int s = it & (STAGES - 1);
        MBAR_WAIT(mb + 8 * s, (it >> 3) & 1);

        const uint32_t ab = sbase + (uint32_t)s * STG_B + aoff;
        const uint32_t bb = sbase + (uint32_t)s * STG_B + A_STG_B + boff;

        // A frags: [mgroup g][khalf h][4]
        uint32_t aFr[2][2][4];
        #pragma unroll
        for (int g = 0; g < 2; g++) {
            const uint32_t rb = ab + (uint32_t)(g * 16 * A_PITCH);
            #pragma unroll
            for (int h = 0; h < 2; h++) {
                const uint32_t kb2 = rb + 32u * h;
                asm volatile("ld.shared.b32 %0, [%1];" : "=r"(aFr[g][h][0]) : "r"(kb2));
                asm volatile("ld.shared.b32 %0, [%1];" : "=r"(aFr[g][h][1]) : "r"(kb2 + 8u * A_PITCH));
                asm volatile("ld.shared.b32 %0, [%1];" : "=r"(aFr[g][h][2]) : "r"(kb2 + 16u));
                asm volatile("ld.shared.b32 %0, [%1];" : "=r"(aFr[g][h][3]) : "r"(kb2 + 8u * A_PITCH + 16u));
            }
        }
        // B frags: 4 n8-groups, uint4 covers k32
        uint4 bFr[4];
        #pragma unroll
        for (int n = 0; n < 4; n++) {
            asm volatile("ld.shared.v4.b32 {%0, %1, %2, %3}, [%4];"
                         : "=r"(bFr[n].x), "=r"(bFr[n].y),
                           "=r"(bFr[n].z), "=r"(bFr[n].w)
                         : "r"(bb + (uint32_t)(n * 8 * B_PITCH)));
        }

        #pragma unroll
        for (int h = 0; h < 2; h++) {
            #pragma unroll
            for (int n = 0; n < 4; n++) {
                uint32_t b0 = h ? bFr[n].z : bFr[n].x;
                uint32_t b1 = h ? bFr[n].w : bFr[n].y;
                mma_f16(acc[0][n], aFr[0][h], b0, b1);
                mma_f16(acc[1][n], aFr[1][h], b0, b1);
            }
        }
        MBAR_ARRIVE(mb + 8 * (STAGES + s));
    }

    // ---- epilogue ----
    const int rBase = m0 + wm * 32 + r4;
    const int cBase = wn * 32 + c4 * 2;
    #pragma unroll
    for (int mi = 0; mi < 2; mi++) {
        #pragma unroll
        for (int ni = 0; ni < 4; ni++) {
            #pragma unroll
            for (int j = 0; j < 4; j++) {
                int row = rBase + mi * 16 + (j >> 1) * 8;
                int col = cBase + ni * 8 + (j & 1);
                float v = acc[mi][ni][j] * scale;
                if (col < 64) v = fmaxf(v, 0.0f);
                if (outT) outT[(size_t)col * NN + kperm2(row)] = __float2half_rn(v);
                else      outR[(size_t)row * NB + col] = v;
            }
        }
    }
}

// ---------------------------------------------------------------------------
extern "C" void kernel_launch(void* const* d_in, const int* in_sizes, int n_in,
                              void* d_out, int out_size) {
    (void)in_sizes; (void)n_in; (void)out_size;
    const float* A = (const float*)d_in[0];
    const float* F = (const float*)d_in[1];
    const float* G = (const float*)d_in[2];
    float* out = (float*)d_out;

    __half *bt1 = nullptr, *bt2 = nullptr;
    cudaGetSymbolAddress((void**)&bt1, g_bth1);
    cudaGetSymbolAddress((void**)&bt2, g_bth2);

    cudaFuncSetAttribute(gemm_layer,
                         cudaFuncAttributeMaxDynamicSharedMemorySize, SMEM_BYTES);

    dim3 pb(32, 8), pg(NN / 32, NB / 32);
    pack_bt_kernel<<<pg, pb>>>(F, G, bt1);

    // layer 1: acc = (2^13 A) @ B ; store fp16( acc * 2^-7 ) = 2^6 * (A@B)
    gemm_layer<<<NN / MT, 384, SMEM_BYTES>>>(A, bt1, bt2, nullptr, 0.0078125f);
    // layer 2: acc = (2^13 A) @ (2^6 h) ; out = acc * 2^-19
    gemm_layer<<<NN / MT, 384, SMEM_BYTES>>>(A, bt2, nullptr, out,
                                             1.0f / 524288.0f);
}